// round 2
// baseline (speedup 1.0000x reference)
#include <cuda_runtime.h>

#define Bsz   8
#define Nseq  1024
#define Cdim  768
#define Hn    12
#define Dh    64
#define Mrows (Bsz * Nseq)            /* 8192 */
#define QSZ   (Bsz * Hn * Nseq * Dh)  /* 6291456 */

// ---------------- scratch (device globals; no allocations allowed) ----------
__device__ float g_q[2][QSZ];
__device__ float g_k[2][QSZ];
__device__ float g_v[2][QSZ];
__device__ float g_ao[2][Mrows * Cdim];   // attention output, [B,N,C]
__device__ float g_z[2][Mrows * Cdim];    // proj output pre-LN

// ---------------- tiled SGEMM: C[m,n] = sum_k A[m,k] * W[n,k] ----------------
// BM=BN=128, BK=16, 256 threads, 8x8 microtile (split 4+4 in both m and n).
// MODE 0: qkv — scatter epilogue into g_q/g_k/g_v (head-major), A = x input.
// MODE 1: proj — add bias, write g_z[z], A = g_ao[z].
template <int MODE>
__global__ void __launch_bounds__(256, 2) gemm128_kernel(
    const float* __restrict__ A0,
    const float* __restrict__ W0, const float* __restrict__ W1,
    const float* __restrict__ bias0, const float* __restrict__ bias1,
    int K)
{
    __shared__ __align__(16) float As[16 * 132];   // As[k][m], pad 4
    __shared__ __align__(16) float Bs[16 * 132];   // Bs[k][n], pad 4

    const int z = blockIdx.z;
    const float* A = (MODE == 0) ? A0 : g_ao[z];
    const float* W = z ? W1 : W0;

    const int tid = threadIdx.x;
    const int tx = tid & 15, ty = tid >> 4;
    const int bm = blockIdx.y * 128, bn = blockIdx.x * 128;

    float acc[8][8];
    #pragma unroll
    for (int i = 0; i < 8; i++)
        #pragma unroll
        for (int j = 0; j < 8; j++) acc[i][j] = 0.f;

    for (int k0 = 0; k0 < K; k0 += 16) {
        #pragma unroll
        for (int it = 0; it < 2; it++) {
            int idx = tid + it * 256;            // 0..511
            int row = idx >> 2;                  // 0..127
            int kc  = (idx & 3) << 2;            // 0,4,8,12
            float4 va = *(const float4*)(A + (size_t)(bm + row) * K + k0 + kc);
            As[(kc + 0) * 132 + row] = va.x; As[(kc + 1) * 132 + row] = va.y;
            As[(kc + 2) * 132 + row] = va.z; As[(kc + 3) * 132 + row] = va.w;
            float4 vb = *(const float4*)(W + (size_t)(bn + row) * K + k0 + kc);
            Bs[(kc + 0) * 132 + row] = vb.x; Bs[(kc + 1) * 132 + row] = vb.y;
            Bs[(kc + 2) * 132 + row] = vb.z; Bs[(kc + 3) * 132 + row] = vb.w;
        }
        __syncthreads();
        #pragma unroll
        for (int kk = 0; kk < 16; kk++) {
            float4 a0 = *(const float4*)&As[kk * 132 + ty * 4];
            float4 a1 = *(const float4*)&As[kk * 132 + 64 + ty * 4];
            float4 b0 = *(const float4*)&Bs[kk * 132 + tx * 4];
            float4 b1 = *(const float4*)&Bs[kk * 132 + 64 + tx * 4];
            float a[8] = {a0.x, a0.y, a0.z, a0.w, a1.x, a1.y, a1.z, a1.w};
            float b[8] = {b0.x, b0.y, b0.z, b0.w, b1.x, b1.y, b1.z, b1.w};
            #pragma unroll
            for (int i = 0; i < 8; i++)
                #pragma unroll
                for (int j = 0; j < 8; j++)
                    acc[i][j] += a[i] * b[j];
        }
        __syncthreads();
    }

    if (MODE == 0) {
        // 128-col block lies entirely within one of q/k/v (boundaries at 768,1536
        // are multiples of 128); each 64-col half is exactly one head.
        #pragma unroll
        for (int half = 0; half < 2; half++) {
            int n0 = bn + half * 64;             // head-aligned
            int which = n0 / Cdim;               // 0=q 1=k 2=v
            int h = (n0 % Cdim) / Dh;
            float* dst = (which == 0) ? g_q[z] : (which == 1) ? g_k[z] : g_v[z];
            #pragma unroll
            for (int i = 0; i < 8; i++) {
                int m = bm + ((i < 4) ? (ty * 4 + i) : (64 + ty * 4 + i - 4));
                int b = m >> 10, nn = m & 1023;
                float4 v = make_float4(acc[i][half * 4 + 0], acc[i][half * 4 + 1],
                                       acc[i][half * 4 + 2], acc[i][half * 4 + 3]);
                *(float4*)&dst[(((size_t)b * Hn + h) * Nseq + nn) * Dh + tx * 4] = v;
            }
        }
    } else {
        const float* bias = z ? bias1 : bias0;
        float* Z = g_z[z];
        #pragma unroll
        for (int half = 0; half < 2; half++) {
            float4 bv = *(const float4*)&bias[bn + half * 64 + tx * 4];
            #pragma unroll
            for (int i = 0; i < 8; i++) {
                int m = bm + ((i < 4) ? (ty * 4 + i) : (64 + ty * 4 + i - 4));
                float4 v = make_float4(acc[i][half * 4 + 0] + bv.x,
                                       acc[i][half * 4 + 1] + bv.y,
                                       acc[i][half * 4 + 2] + bv.z,
                                       acc[i][half * 4 + 3] + bv.w);
                *(float4*)&Z[(size_t)m * Cdim + bn + half * 64 + tx * 4] = v;
            }
        }
    }
}

// ---------------- Gram-Schmidt ortho + saliency (warp per (b,n)) ------------
__global__ void __launch_bounds__(128) ortho_kernel(
    const float* __restrict__ orth_scale_p, float* __restrict__ sal_out)
{
    int warp = (blockIdx.x * blockDim.x + threadIdx.x) >> 5;
    int lane = threadIdx.x & 31;
    if (warp >= Mrows) return;
    int b = warp >> 10, nn = warp & 1023;

    float scale = fminf(fmaxf(*orth_scale_p, 0.f), 1.f);
    float sal = 0.f;
    #pragma unroll
    for (int h = 0; h < Hn; h++) {
        size_t base = (((size_t)b * Hn + h) * Nseq + nn) * Dh;
        float qi0 = g_q[0][base + lane],      qi1 = g_q[0][base + 32 + lane];
        float qc0 = g_q[1][base + lane],      qc1 = g_q[1][base + 32 + lane];
        float dot = qi0 * qc0 + qi1 * qc1;
        float nsq = qc0 * qc0 + qc1 * qc1;
        #pragma unroll
        for (int o = 16; o > 0; o >>= 1) {
            dot += __shfl_xor_sync(0xffffffffu, dot, o);
            nsq += __shfl_xor_sync(0xffffffffu, nsq, o);
        }
        nsq += 1e-5f;
        float coeff = fminf(fmaxf(dot / nsq, -1.f), 1.f);
        float f = scale * coeff;
        g_q[0][base + lane]      = qi0 - f * qc0;
        g_q[0][base + 32 + lane] = qi1 - f * qc1;
        sal += fabsf(dot) * rsqrtf(nsq);
    }
    if (lane == 0)
        sal_out[warp] = fminf(sal * (1.f / (float)Hn), 1.f);
}

// ---------------- attention: 128q x 128kv tiles, fp32 flash -----------------
// clip(s,-20,20) then softmax == exp(s-20)/sum(exp(s-20)) exactly (max<=20).
// smem: Qs[d][q] 64x132 | KV buf: Ks[d][j] 64x132 / Vs[j][d] 128x68 | Ps[q][j]
// 128x132 | denom[128].
#define QS_OFF   0
#define KV_OFF   (64 * 132)                    /* 8448 */
#define PS_OFF   (KV_OFF + 128 * 68)           /* 8448 + 8704 = 17152 */
#define DEN_OFF  (PS_OFF + 128 * 132)          /* 17152 + 16896 = 34048 */
#define ATTN_SMEM_FLOATS (DEN_OFF + 128)       /* 34176 -> 136704 B */

__global__ void __launch_bounds__(256, 1) attn_kernel()
{
    extern __shared__ __align__(16) float sm[];
    float* Qs    = sm + QS_OFF;
    float* KVs   = sm + KV_OFF;
    float* Ps    = sm + PS_OFF;
    float* denom = sm + DEN_OFF;

    const int z  = blockIdx.z;
    const int bh = blockIdx.y;               // 0..95
    const int q0 = blockIdx.x * 128;
    const float* Q = g_q[z] + (size_t)bh * Nseq * Dh;
    const float* K = g_k[z] + (size_t)bh * Nseq * Dh;
    const float* V = g_v[z] + (size_t)bh * Nseq * Dh;

    const int tid = threadIdx.x;
    const int tx = tid & 15, ty = tid >> 4;
    int rowi[8];
    #pragma unroll
    for (int i = 0; i < 8; i++)
        rowi[i] = (i < 4) ? (ty * 4 + i) : (64 + ty * 4 + i - 4);

    // Q tile transposed: Qs[d][q]
    #pragma unroll
    for (int it = 0; it < 8; it++) {
        int idx = tid + it * 256;            // 0..2047
        int row = idx >> 4;                  // q 0..127
        int kc  = (idx & 15) << 2;           // d 0..60
        float4 v = *(const float4*)(Q + (size_t)(q0 + row) * Dh + kc);
        Qs[(kc + 0) * 132 + row] = v.x; Qs[(kc + 1) * 132 + row] = v.y;
        Qs[(kc + 2) * 132 + row] = v.z; Qs[(kc + 3) * 132 + row] = v.w;
    }
    if (tid < 128) denom[tid] = 0.f;

    float acc[8][4];
    #pragma unroll
    for (int i = 0; i < 8; i++)
        #pragma unroll
        for (int j = 0; j < 4; j++) acc[i][j] = 0.f;
    float rs[8] = {};

    for (int j0 = 0; j0 < Nseq; j0 += 128) {
        // K tile transposed: Ks[d][j]
        #pragma unroll
        for (int it = 0; it < 8; it++) {
            int idx = tid + it * 256;
            int row = idx >> 4;              // j 0..127
            int kc  = (idx & 15) << 2;
            float4 v = *(const float4*)(K + (size_t)(j0 + row) * Dh + kc);
            KVs[(kc + 0) * 132 + row] = v.x; KVs[(kc + 1) * 132 + row] = v.y;
            KVs[(kc + 2) * 132 + row] = v.z; KVs[(kc + 3) * 132 + row] = v.w;
        }
        __syncthreads();

        float s[8][8];
        #pragma unroll
        for (int i = 0; i < 8; i++)
            #pragma unroll
            for (int j = 0; j < 8; j++) s[i][j] = 0.f;
        #pragma unroll
        for (int dd = 0; dd < 64; dd++) {
            float4 a0 = *(const float4*)&Qs[dd * 132 + ty * 4];
            float4 a1 = *(const float4*)&Qs[dd * 132 + 64 + ty * 4];
            float4 b0 = *(const float4*)&KVs[dd * 132 + tx * 4];
            float4 b1 = *(const float4*)&KVs[dd * 132 + 64 + tx * 4];
            float a[8] = {a0.x, a0.y, a0.z, a0.w, a1.x, a1.y, a1.z, a1.w};
            float b[8] = {b0.x, b0.y, b0.z, b0.w, b1.x, b1.y, b1.z, b1.w};
            #pragma unroll
            for (int i = 0; i < 8; i++)
                #pragma unroll
                for (int j = 0; j < 8; j++)
                    s[i][j] += a[i] * b[j];
        }
        // e = exp(clip(s/8) - 20) -> Ps[q][j]; row-sum partials in registers
        #pragma unroll
        for (int i = 0; i < 8; i++) {
            float p[8];
            #pragma unroll
            for (int j = 0; j < 8; j++) {
                float sv = fminf(fmaxf(s[i][j] * 0.125f, -20.f), 20.f);
                p[j] = __expf(sv - 20.f);
                rs[i] += p[j];
            }
            *(float4*)&Ps[rowi[i] * 132 + tx * 4]      = make_float4(p[0], p[1], p[2], p[3]);
            *(float4*)&Ps[rowi[i] * 132 + 64 + tx * 4] = make_float4(p[4], p[5], p[6], p[7]);
        }
        __syncthreads();   // Ps ready, Ks consumed

        // V tile natural: Vs[j][d], stride 68
        #pragma unroll
        for (int it = 0; it < 8; it++) {
            int idx = tid + it * 256;
            int row = idx >> 4;
            int kc  = (idx & 15) << 2;
            float4 v = *(const float4*)(V + (size_t)(j0 + row) * Dh + kc);
            *(float4*)&KVs[row * 68 + kc] = v;
        }
        __syncthreads();   // Vs ready

        #pragma unroll 4
        for (int jj = 0; jj < 128; jj += 4) {
            float4 pa[8];
            #pragma unroll
            for (int i = 0; i < 8; i++)
                pa[i] = *(const float4*)&Ps[rowi[i] * 132 + jj];
            float4 vb[4];
            #pragma unroll
            for (int r = 0; r < 4; r++)
                vb[r] = *(const float4*)&KVs[(jj + r) * 68 + tx * 4];
            #pragma unroll
            for (int i = 0; i < 8; i++) {
                acc[i][0] += pa[i].x * vb[0].x + pa[i].y * vb[1].x + pa[i].z * vb[2].x + pa[i].w * vb[3].x;
                acc[i][1] += pa[i].x * vb[0].y + pa[i].y * vb[1].y + pa[i].z * vb[2].y + pa[i].w * vb[3].y;
                acc[i][2] += pa[i].x * vb[0].z + pa[i].y * vb[1].z + pa[i].z * vb[2].z + pa[i].w * vb[3].z;
                acc[i][3] += pa[i].x * vb[0].w + pa[i].y * vb[1].w + pa[i].z * vb[2].w + pa[i].w * vb[3].w;
            }
        }
        __syncthreads();   // before KVs/Ps rewrite next tile
    }

    // denominators: reduce register partials across the 16 tx-groups
    #pragma unroll
    for (int i = 0; i < 8; i++)
        atomicAdd(&denom[rowi[i]], rs[i]);
    __syncthreads();

    // epilogue: out[b,n, h*64+d] = acc / denom
    const int b = bh / Hn, h = bh % Hn;
    float* O = g_ao[z];
    #pragma unroll
    for (int i = 0; i < 8; i++) {
        int q = q0 + rowi[i];
        float inv = 1.f / denom[rowi[i]];
        float4 v = make_float4(acc[i][0] * inv, acc[i][1] * inv,
                               acc[i][2] * inv, acc[i][3] * inv);
        *(float4*)&O[((size_t)(b * Nseq + q)) * Cdim + h * Dh + tx * 4] = v;
    }
}

// ---------------- LayerNorm (row per block) ---------------------------------
__global__ void __launch_bounds__(256) ln_kernel(
    const float* __restrict__ w0, const float* __restrict__ b0,
    const float* __restrict__ w1, const float* __restrict__ b1,
    float* __restrict__ out)
{
    const int z = blockIdx.y, m = blockIdx.x, tid = threadIdx.x;
    const float* row = g_z[z] + (size_t)m * Cdim;
    float v0 = row[tid], v1 = row[tid + 256], v2 = row[tid + 512];
    float s  = v0 + v1 + v2;
    float sq = v0 * v0 + v1 * v1 + v2 * v2;
    #pragma unroll
    for (int o = 16; o > 0; o >>= 1) {
        s  += __shfl_xor_sync(0xffffffffu, s,  o);
        sq += __shfl_xor_sync(0xffffffffu, sq, o);
    }
    __shared__ float ss[8], sqs[8];
    int wid = tid >> 5, lane = tid & 31;
    if (lane == 0) { ss[wid] = s; sqs[wid] = sq; }
    __syncthreads();
    if (tid == 0) {
        float S = 0.f, Qq = 0.f;
        #pragma unroll
        for (int i = 0; i < 8; i++) { S += ss[i]; Qq += sqs[i]; }
        float mean = S * (1.f / (float)Cdim);
        float var  = Qq * (1.f / (float)Cdim) - mean * mean;
        ss[0] = mean; sqs[0] = rsqrtf(var + 1e-5f);
    }
    __syncthreads();
    float mean = ss[0], rstd = sqs[0];
    const float* w = z ? w1 : w0;
    const float* bb = z ? b1 : b0;
    float* o = out + (size_t)z * Mrows * Cdim + (size_t)m * Cdim;
    o[tid]       = (v0 - mean) * rstd * w[tid]       + bb[tid];
    o[tid + 256] = (v1 - mean) * rstd * w[tid + 256] + bb[tid + 256];
    o[tid + 512] = (v2 - mean) * rstd * w[tid + 512] + bb[tid + 512];
}

// ---------------- launch -----------------------------------------------------
extern "C" void kernel_launch(void* const* d_in, const int* in_sizes, int n_in,
                              void* d_out, int out_size)
{
    const float* x        = (const float*)d_in[0];
    const float* wqkv_id  = (const float*)d_in[1];
    const float* wqkv_cl  = (const float*)d_in[2];
    const float* wp_id    = (const float*)d_in[3];
    const float* bp_id    = (const float*)d_in[4];
    const float* wp_cl    = (const float*)d_in[5];
    const float* bp_cl    = (const float*)d_in[6];
    const float* lnw_id   = (const float*)d_in[7];
    const float* lnb_id   = (const float*)d_in[8];
    const float* lnw_cl   = (const float*)d_in[9];
    const float* lnb_cl   = (const float*)d_in[10];
    const float* orth     = (const float*)d_in[11];
    float* out = (float*)d_out;

    const int attn_smem = ATTN_SMEM_FLOATS * (int)sizeof(float);  // ~133.5 KB
    cudaFuncSetAttribute(attn_kernel,
                         cudaFuncAttributeMaxDynamicSharedMemorySize, attn_smem);

    // 1. QKV GEMMs (both streams): [8192 x 2304] = x @ Wqkv^T
    dim3 g1(3 * Cdim / 128, Mrows / 128, 2);        // (18, 64, 2)
    gemm128_kernel<0><<<g1, 256>>>(x, wqkv_id, wqkv_cl, nullptr, nullptr, Cdim);

    // 2. ortho projection of q_id + saliency (written directly to d_out tail)
    ortho_kernel<<<Mrows / 4, 128>>>(orth, out + 2 * (size_t)Mrows * Cdim);

    // 3. attention (both streams)
    attn_kernel<<<dim3(Nseq / 128, Bsz * Hn, 2), 256, attn_smem>>>();

    // 4. proj + bias (both streams): [8192 x 768]
    dim3 g2(Cdim / 128, Mrows / 128, 2);            // (6, 64, 2)
    gemm128_kernel<1><<<g2, 256>>>(nullptr, wp_id, wp_cl, bp_id, bp_cl, Cdim);

    // 5. layernorm -> d_out
    ln_kernel<<<dim3(Mrows, 2), 256>>>(lnw_id, lnb_id, lnw_cl, lnb_cl, out);
}

// round 5
// speedup vs baseline: 1.3573x; 1.3573x over previous
#include <cuda_runtime.h>
#include <cuda_bf16.h>
#include <cstdint>

#define Bsz   8
#define Nseq  1024
#define Cdim  768
#define Hn    12
#define Dh    64
#define Mrows (Bsz * Nseq)            /* 8192 */
#define QSZ   (Bsz * Hn * Nseq * Dh)  /* 6291456 */

// ---------------- scratch (device globals; no allocations allowed) ----------
__device__ float g_q[2][QSZ];
__device__ float g_k[2][QSZ];
__device__ float g_v[2][QSZ];
__device__ float g_ao[2][Mrows * Cdim];   // attention output, [B,N,C]
__device__ float g_z[2][Mrows * Cdim];    // proj output pre-LN

// bf16 hi/lo split operands for tensor-core GEMMs (16B-aligned: vector access)
__device__ __align__(16) __nv_bfloat16 g_xh[Mrows * Cdim],  g_xl[Mrows * Cdim];
__device__ __align__(16) __nv_bfloat16 g_wqh[2][3 * Cdim * Cdim], g_wql[2][3 * Cdim * Cdim];
__device__ __align__(16) __nv_bfloat16 g_wph[2][Cdim * Cdim],     g_wpl[2][Cdim * Cdim];
__device__ __align__(16) __nv_bfloat16 g_aoh[2][Mrows * Cdim],    g_aol[2][Mrows * Cdim];

// ---------------- portable tensor-core helpers (compute_103-safe) -----------
__device__ __forceinline__ uint32_t smem_to_u32(const void* p) {
    uint32_t a;
    asm("{ .reg .u64 t; cvta.to.shared.u64 t, %1; cvt.u32.u64 %0, t; }"
        : "=r"(a) : "l"(p));
    return a;
}
__device__ __forceinline__ void ldsm4(uint32_t* r, uint32_t addr) {
    asm volatile("ldmatrix.sync.aligned.m8n8.x4.shared.b16 {%0,%1,%2,%3}, [%4];"
        : "=r"(r[0]), "=r"(r[1]), "=r"(r[2]), "=r"(r[3]) : "r"(addr));
}
__device__ __forceinline__ void mma16816(float* d, const uint32_t* a,
                                         uint32_t b0, uint32_t b1) {
    asm volatile("mma.sync.aligned.m16n8k16.row.col.f32.bf16.bf16.f32 "
        "{%0,%1,%2,%3}, {%4,%5,%6,%7}, {%8,%9}, {%0,%1,%2,%3};"
        : "+f"(d[0]), "+f"(d[1]), "+f"(d[2]), "+f"(d[3])
        : "r"(a[0]), "r"(a[1]), "r"(a[2]), "r"(a[3]), "r"(b0), "r"(b1));
}

// ---------------- fp32 -> bf16 hi/lo split -----------------------------------
__global__ void __launch_bounds__(256) cvt_kernel(
    const float4* __restrict__ s, __nv_bfloat162* __restrict__ h,
    __nv_bfloat162* __restrict__ l, int n4)
{
    int i = blockIdx.x * 256 + threadIdx.x;
    if (i >= n4) return;
    float4 v = s[i];
    __nv_bfloat16 h0 = __float2bfloat16(v.x), h1 = __float2bfloat16(v.y);
    __nv_bfloat16 h2 = __float2bfloat16(v.z), h3 = __float2bfloat16(v.w);
    h[i * 2 + 0] = __nv_bfloat162(h0, h1);
    h[i * 2 + 1] = __nv_bfloat162(h2, h3);
    l[i * 2 + 0] = __nv_bfloat162(__float2bfloat16(v.x - __bfloat162float(h0)),
                                  __float2bfloat16(v.y - __bfloat162float(h1)));
    l[i * 2 + 1] = __nv_bfloat162(__float2bfloat16(v.z - __bfloat162float(h2)),
                                  __float2bfloat16(v.w - __bfloat162float(h3)));
}

// ---------------- HMMA GEMM: C[m,n] = sum_k A[m,k]*W[n,k] --------------------
// BM=BN=128, BK=32, 256 threads (8 warps: 4m x 2n), m16n8k16 bf16 Karatsuba
// (ah*bh + ah*bl + al*bh, fp32 accumulate). Register-prefetch single-buffer.
// MODE 0: qkv -> scatter into g_q/g_k/g_v.  MODE 1: proj + bias -> g_z.
#define SROW 40                    /* bf16 per smem row (32 data + 8 pad)     */
#define MATS (128 * SROW)          /* 5120 bf16 per matrix tile               */

template <int MODE>
__global__ void __launch_bounds__(256) mma_gemm_kernel(
    const __nv_bfloat16* __restrict__ Ah0, const __nv_bfloat16* __restrict__ Al0,
    const float* __restrict__ bias0, const float* __restrict__ bias1)
{
    __shared__ __align__(16) __nv_bfloat16 sb[4 * MATS];   // Ah | Al | Bh | Bl

    const int z = blockIdx.z, tid = threadIdx.x;
    const int wid = tid >> 5, lane = tid & 31;
    const int bm = blockIdx.y * 128, bn = blockIdx.x * 128;
    const int wm = (wid >> 1) * 32, wn = (wid & 1) * 64;

    const __nv_bfloat16* src[4] = {
        (MODE == 0) ? Ah0 : g_aoh[z], (MODE == 0) ? Al0 : g_aol[z],
        (MODE == 0) ? g_wqh[z] : g_wph[z], (MODE == 0) ? g_wql[z] : g_wpl[z] };
    const int rb[4] = {bm, bm, bn, bn};

    const int prow = tid >> 2;               // 0..63 (+64 for second half)
    const int pseg = (tid & 3) * 8;          // bf16 offset of 16B segment

    uint4 pre[4][2];
    #pragma unroll
    for (int m = 0; m < 4; m++)
        #pragma unroll
        for (int it = 0; it < 2; it++)
            pre[m][it] = *(const uint4*)(src[m] +
                (size_t)(rb[m] + prow + it * 64) * Cdim + pseg);

    float acc[2][8][4] = {};
    const uint32_t sbase = smem_to_u32(sb);

    for (int c = 0; c < 24; c++) {
        __syncthreads();                      // prior reads of sb complete
        #pragma unroll
        for (int m = 0; m < 4; m++)
            #pragma unroll
            for (int it = 0; it < 2; it++)
                *(uint4*)&sb[m * MATS + (prow + it * 64) * SROW + pseg] = pre[m][it];
        __syncthreads();
        if (c < 23) {
            const int kc = (c + 1) * 32;
            #pragma unroll
            for (int m = 0; m < 4; m++)
                #pragma unroll
                for (int it = 0; it < 2; it++)
                    pre[m][it] = *(const uint4*)(src[m] +
                        (size_t)(rb[m] + prow + it * 64) * Cdim + kc + pseg);
        }
        #pragma unroll
        for (int ks = 0; ks < 2; ks++) {
            const uint32_t koff = (uint32_t)(ks * 16 + (lane >> 4) * 8) * 2;
            uint32_t ah[2][4], al[2][4];
            #pragma unroll
            for (int mt = 0; mt < 2; mt++) {
                uint32_t ro = (uint32_t)(wm + mt * 16 + (lane & 15)) * SROW * 2 + koff;
                ldsm4(ah[mt], sbase + ro);                     // Ah at offset 0
                ldsm4(al[mt], sbase + MATS * 2 + ro);          // Al
            }
            #pragma unroll
            for (int u = 0; u < 4; u++) {
                uint32_t ro = (uint32_t)(wn + u * 16 + (lane & 15)) * SROW * 2 + koff;
                uint32_t bh[4], bl[4];
                ldsm4(bh, sbase + 2 * MATS * 2 + ro);
                ldsm4(bl, sbase + 3 * MATS * 2 + ro);
                #pragma unroll
                for (int mt = 0; mt < 2; mt++) {
                    #pragma unroll
                    for (int hf = 0; hf < 2; hf++) {
                        float* d = acc[mt][u * 2 + hf];
                        uint32_t b0 = hf ? bh[1] : bh[0], b1 = hf ? bh[3] : bh[2];
                        uint32_t l0 = hf ? bl[1] : bl[0], l1 = hf ? bl[3] : bl[2];
                        mma16816(d, ah[mt], b0, b1);
                        mma16816(d, ah[mt], l0, l1);
                        mma16816(d, al[mt], b0, b1);
                    }
                }
            }
        }
    }

    // epilogue: d0=(g,2c) d1=(g,2c+1) d2=(g+8,2c) d3=(g+8,2c+1)
    const int g = lane >> 2, cc = (lane & 3) * 2;
    #pragma unroll
    for (int mt = 0; mt < 2; mt++) {
        #pragma unroll
        for (int nt = 0; nt < 8; nt++) {
            const int n0 = bn + wn + nt * 8 + cc;
            const int m0 = bm + wm + mt * 16 + g;
            const float* a = acc[mt][nt];
            if (MODE == 0) {
                int which = n0 / Cdim, h = (n0 % Cdim) / Dh, d0 = n0 % Dh;
                float* dst = (which == 0) ? g_q[z] : (which == 1) ? g_k[z] : g_v[z];
                int b0i = m0 >> 10, nn0 = m0 & 1023;
                *(float2*)&dst[(((size_t)b0i * Hn + h) * Nseq + nn0) * Dh + d0] =
                    make_float2(a[0], a[1]);
                int m1 = m0 + 8, b1i = m1 >> 10, nn1 = m1 & 1023;
                *(float2*)&dst[(((size_t)b1i * Hn + h) * Nseq + nn1) * Dh + d0] =
                    make_float2(a[2], a[3]);
            } else {
                const float* bias = z ? bias1 : bias0;
                float bx0 = bias[n0], bx1 = bias[n0 + 1];
                *(float2*)&g_z[z][(size_t)m0 * Cdim + n0] =
                    make_float2(a[0] + bx0, a[1] + bx1);
                *(float2*)&g_z[z][(size_t)(m0 + 8) * Cdim + n0] =
                    make_float2(a[2] + bx0, a[3] + bx1);
            }
        }
    }
}

// ---------------- Gram-Schmidt ortho + saliency (warp per (b,n)) ------------
__global__ void __launch_bounds__(128) ortho_kernel(
    const float* __restrict__ orth_scale_p, float* __restrict__ sal_out)
{
    int warp = (blockIdx.x * blockDim.x + threadIdx.x) >> 5;
    int lane = threadIdx.x & 31;
    if (warp >= Mrows) return;
    int b = warp >> 10, nn = warp & 1023;

    float scale = fminf(fmaxf(*orth_scale_p, 0.f), 1.f);
    float sal = 0.f;
    #pragma unroll
    for (int h = 0; h < Hn; h++) {
        size_t base = (((size_t)b * Hn + h) * Nseq + nn) * Dh;
        float qi0 = g_q[0][base + lane],      qi1 = g_q[0][base + 32 + lane];
        float qc0 = g_q[1][base + lane],      qc1 = g_q[1][base + 32 + lane];
        float dot = qi0 * qc0 + qi1 * qc1;
        float nsq = qc0 * qc0 + qc1 * qc1;
        #pragma unroll
        for (int o = 16; o > 0; o >>= 1) {
            dot += __shfl_xor_sync(0xffffffffu, dot, o);
            nsq += __shfl_xor_sync(0xffffffffu, nsq, o);
        }
        nsq += 1e-5f;
        float coeff = fminf(fmaxf(dot / nsq, -1.f), 1.f);
        float f = scale * coeff;
        g_q[0][base + lane]      = qi0 - f * qc0;
        g_q[0][base + 32 + lane] = qi1 - f * qc1;
        sal += fabsf(dot) * rsqrtf(nsq);
    }
    if (lane == 0)
        sal_out[warp] = fminf(sal * (1.f / (float)Hn), 1.f);
}

// ---------------- attention: 128q x 128kv tiles, fp32 flash -----------------
// clip(s,-20,20) then softmax == exp(s-20)/sum(exp(s-20)) exactly (max<=20).
#define QS_OFF   0
#define KV_OFF   (64 * 132)
#define PS_OFF   (KV_OFF + 128 * 68)
#define DEN_OFF  (PS_OFF + 128 * 132)
#define ATTN_SMEM_FLOATS (DEN_OFF + 128)

__global__ void __launch_bounds__(256, 1) attn_kernel()
{
    extern __shared__ __align__(16) float sm[];
    float* Qs    = sm + QS_OFF;
    float* KVs   = sm + KV_OFF;
    float* Ps    = sm + PS_OFF;
    float* denom = sm + DEN_OFF;

    const int z  = blockIdx.z;
    const int bh = blockIdx.y;
    const int q0 = blockIdx.x * 128;
    const float* Q = g_q[z] + (size_t)bh * Nseq * Dh;
    const float* K = g_k[z] + (size_t)bh * Nseq * Dh;
    const float* V = g_v[z] + (size_t)bh * Nseq * Dh;

    const int tid = threadIdx.x;
    const int tx = tid & 15, ty = tid >> 4;
    int rowi[8];
    #pragma unroll
    for (int i = 0; i < 8; i++)
        rowi[i] = (i < 4) ? (ty * 4 + i) : (64 + ty * 4 + i - 4);

    #pragma unroll
    for (int it = 0; it < 8; it++) {
        int idx = tid + it * 256;
        int row = idx >> 4;
        int kc  = (idx & 15) << 2;
        float4 v = *(const float4*)(Q + (size_t)(q0 + row) * Dh + kc);
        Qs[(kc + 0) * 132 + row] = v.x; Qs[(kc + 1) * 132 + row] = v.y;
        Qs[(kc + 2) * 132 + row] = v.z; Qs[(kc + 3) * 132 + row] = v.w;
    }
    if (tid < 128) denom[tid] = 0.f;

    float acc[8][4];
    #pragma unroll
    for (int i = 0; i < 8; i++)
        #pragma unroll
        for (int j = 0; j < 4; j++) acc[i][j] = 0.f;
    float rs[8] = {};

    for (int j0 = 0; j0 < Nseq; j0 += 128) {
        #pragma unroll
        for (int it = 0; it < 8; it++) {
            int idx = tid + it * 256;
            int row = idx >> 4;
            int kc  = (idx & 15) << 2;
            float4 v = *(const float4*)(K + (size_t)(j0 + row) * Dh + kc);
            KVs[(kc + 0) * 132 + row] = v.x; KVs[(kc + 1) * 132 + row] = v.y;
            KVs[(kc + 2) * 132 + row] = v.z; KVs[(kc + 3) * 132 + row] = v.w;
        }
        __syncthreads();

        float s[8][8];
        #pragma unroll
        for (int i = 0; i < 8; i++)
            #pragma unroll
            for (int j = 0; j < 8; j++) s[i][j] = 0.f;
        #pragma unroll
        for (int dd = 0; dd < 64; dd++) {
            float4 a0 = *(const float4*)&Qs[dd * 132 + ty * 4];
            float4 a1 = *(const float4*)&Qs[dd * 132 + 64 + ty * 4];
            float4 b0 = *(const float4*)&KVs[dd * 132 + tx * 4];
            float4 b1 = *(const float4*)&KVs[dd * 132 + 64 + tx * 4];
            float a[8] = {a0.x, a0.y, a0.z, a0.w, a1.x, a1.y, a1.z, a1.w};
            float b[8] = {b0.x, b0.y, b0.z, b0.w, b1.x, b1.y, b1.z, b1.w};
            #pragma unroll
            for (int i = 0; i < 8; i++)
                #pragma unroll
                for (int j = 0; j < 8; j++)
                    s[i][j] += a[i] * b[j];
        }
        #pragma unroll
        for (int i = 0; i < 8; i++) {
            float p[8];
            #pragma unroll
            for (int j = 0; j < 8; j++) {
                float sv = fminf(fmaxf(s[i][j] * 0.125f, -20.f), 20.f);
                p[j] = __expf(sv - 20.f);
                rs[i] += p[j];
            }
            *(float4*)&Ps[rowi[i] * 132 + tx * 4]      = make_float4(p[0], p[1], p[2], p[3]);
            *(float4*)&Ps[rowi[i] * 132 + 64 + tx * 4] = make_float4(p[4], p[5], p[6], p[7]);
        }
        __syncthreads();

        #pragma unroll
        for (int it = 0; it < 8; it++) {
            int idx = tid + it * 256;
            int row = idx >> 4;
            int kc  = (idx & 15) << 2;
            float4 v = *(const float4*)(V + (size_t)(j0 + row) * Dh + kc);
            *(float4*)&KVs[row * 68 + kc] = v;
        }
        __syncthreads();

        #pragma unroll 4
        for (int jj = 0; jj < 128; jj += 4) {
            float4 pa[8];
            #pragma unroll
            for (int i = 0; i < 8; i++)
                pa[i] = *(const float4*)&Ps[rowi[i] * 132 + jj];
            float4 vb[4];
            #pragma unroll
            for (int r = 0; r < 4; r++)
                vb[r] = *(const float4*)&KVs[(jj + r) * 68 + tx * 4];
            #pragma unroll
            for (int i = 0; i < 8; i++) {
                acc[i][0] += pa[i].x * vb[0].x + pa[i].y * vb[1].x + pa[i].z * vb[2].x + pa[i].w * vb[3].x;
                acc[i][1] += pa[i].x * vb[0].y + pa[i].y * vb[1].y + pa[i].z * vb[2].y + pa[i].w * vb[3].y;
                acc[i][2] += pa[i].x * vb[0].z + pa[i].y * vb[1].z + pa[i].z * vb[2].z + pa[i].w * vb[3].z;
                acc[i][3] += pa[i].x * vb[0].w + pa[i].y * vb[1].w + pa[i].z * vb[2].w + pa[i].w * vb[3].w;
            }
        }
        __syncthreads();
    }

    #pragma unroll
    for (int i = 0; i < 8; i++)
        atomicAdd(&denom[rowi[i]], rs[i]);
    __syncthreads();

    const int b = bh / Hn, h = bh % Hn;
    float* O = g_ao[z];
    #pragma unroll
    for (int i = 0; i < 8; i++) {
        int q = q0 + rowi[i];
        float inv = 1.f / denom[rowi[i]];
        float4 v = make_float4(acc[i][0] * inv, acc[i][1] * inv,
                               acc[i][2] * inv, acc[i][3] * inv);
        *(float4*)&O[((size_t)(b * Nseq + q)) * Cdim + h * Dh + tx * 4] = v;
    }
}

// ---------------- LayerNorm (row per block) ---------------------------------
__global__ void __launch_bounds__(256) ln_kernel(
    const float* __restrict__ w0, const float* __restrict__ b0,
    const float* __restrict__ w1, const float* __restrict__ b1,
    float* __restrict__ out)
{
    const int z = blockIdx.y, m = blockIdx.x, tid = threadIdx.x;
    const float* row = g_z[z] + (size_t)m * Cdim;
    float v0 = row[tid], v1 = row[tid + 256], v2 = row[tid + 512];
    float s  = v0 + v1 + v2;
    float sq = v0 * v0 + v1 * v1 + v2 * v2;
    #pragma unroll
    for (int o = 16; o > 0; o >>= 1) {
        s  += __shfl_xor_sync(0xffffffffu, s,  o);
        sq += __shfl_xor_sync(0xffffffffu, sq, o);
    }
    __shared__ float ss[8], sqs[8];
    int wid = tid >> 5, lane = tid & 31;
    if (lane == 0) { ss[wid] = s; sqs[wid] = sq; }
    __syncthreads();
    if (tid == 0) {
        float S = 0.f, Qq = 0.f;
        #pragma unroll
        for (int i = 0; i < 8; i++) { S += ss[i]; Qq += sqs[i]; }
        float mean = S * (1.f / (float)Cdim);
        float var  = Qq * (1.f / (float)Cdim) - mean * mean;
        ss[0] = mean; sqs[0] = rsqrtf(var + 1e-5f);
    }
    __syncthreads();
    float mean = ss[0], rstd = sqs[0];
    const float* w = z ? w1 : w0;
    const float* bb = z ? b1 : b0;
    float* o = out + (size_t)z * Mrows * Cdim + (size_t)m * Cdim;
    o[tid]       = (v0 - mean) * rstd * w[tid]       + bb[tid];
    o[tid + 256] = (v1 - mean) * rstd * w[tid + 256] + bb[tid + 256];
    o[tid + 512] = (v2 - mean) * rstd * w[tid + 512] + bb[tid + 512];
}

// ---------------- launch -----------------------------------------------------
static void cvt(const float* src, __nv_bfloat16* hi, __nv_bfloat16* lo, int n) {
    int n4 = n / 4;
    cvt_kernel<<<(n4 + 255) / 256, 256>>>(
        (const float4*)src, (__nv_bfloat162*)hi, (__nv_bfloat162*)lo, n4);
}

extern "C" void kernel_launch(void* const* d_in, const int* in_sizes, int n_in,
                              void* d_out, int out_size)
{
    const float* x        = (const float*)d_in[0];
    const float* wqkv_id  = (const float*)d_in[1];
    const float* wqkv_cl  = (const float*)d_in[2];
    const float* wp_id    = (const float*)d_in[3];
    const float* bp_id    = (const float*)d_in[4];
    const float* wp_cl    = (const float*)d_in[5];
    const float* bp_cl    = (const float*)d_in[6];
    const float* lnw_id   = (const float*)d_in[7];
    const float* lnb_id   = (const float*)d_in[8];
    const float* lnw_cl   = (const float*)d_in[9];
    const float* lnb_cl   = (const float*)d_in[10];
    const float* orth     = (const float*)d_in[11];
    float* out = (float*)d_out;

    const int attn_smem = ATTN_SMEM_FLOATS * (int)sizeof(float);
    cudaFuncSetAttribute(attn_kernel,
                         cudaFuncAttributeMaxDynamicSharedMemorySize, attn_smem);

    __nv_bfloat16 *xh, *xl, *wqh, *wql, *wph, *wpl, *aoh, *aol;
    cudaGetSymbolAddress((void**)&xh,  g_xh);
    cudaGetSymbolAddress((void**)&xl,  g_xl);
    cudaGetSymbolAddress((void**)&wqh, g_wqh);
    cudaGetSymbolAddress((void**)&wql, g_wql);
    cudaGetSymbolAddress((void**)&wph, g_wph);
    cudaGetSymbolAddress((void**)&wpl, g_wpl);
    cudaGetSymbolAddress((void**)&aoh, g_aoh);
    cudaGetSymbolAddress((void**)&aol, g_aol);

    // 0. fp32 -> bf16 hi/lo splits
    cvt(x,        xh,                       xl,                       Mrows * Cdim);
    cvt(wqkv_id,  wqh,                      wql,                      3 * Cdim * Cdim);
    cvt(wqkv_cl,  wqh + 3 * Cdim * Cdim,    wql + 3 * Cdim * Cdim,    3 * Cdim * Cdim);
    cvt(wp_id,    wph,                      wpl,                      Cdim * Cdim);
    cvt(wp_cl,    wph + Cdim * Cdim,        wpl + Cdim * Cdim,        Cdim * Cdim);

    // 1. QKV GEMMs on HMMA tensor cores (both streams)
    dim3 g1(3 * Cdim / 128, Mrows / 128, 2);      // (18, 64, 2)
    mma_gemm_kernel<0><<<g1, 256>>>(xh, xl, nullptr, nullptr);

    // 2. ortho projection of q_id + saliency
    ortho_kernel<<<Mrows / 4, 128>>>(orth, out + 2 * (size_t)Mrows * Cdim);

    // 3. attention (both streams)
    attn_kernel<<<dim3(Nseq / 128, Bsz * Hn, 2), 256, attn_smem>>>();

    // 4. split attention output, then proj GEMM on HMMA
    {
        float* ao;
        cudaGetSymbolAddress((void**)&ao, g_ao);
        cvt(ao, aoh, aol, 2 * Mrows * Cdim);
    }
    dim3 g2(Cdim / 128, Mrows / 128, 2);          // (6, 64, 2)
    mma_gemm_kernel<1><<<g2, 256>>>(nullptr, nullptr, bp_id, bp_cl);

    // 5. layernorm -> d_out
    ln_kernel<<<dim3(Mrows, 2), 256>>>(lnw_id, lnb_id, lnw_cl, lnb_cl, out);
}

// round 8
// speedup vs baseline: 1.7700x; 1.3040x over previous
#include <cuda_runtime.h>
#include <cuda_bf16.h>
#include <cstdint>

#define Bsz   8
#define Nseq  1024
#define Cdim  768
#define Hn    12
#define Dh    64
#define Mrows (Bsz * Nseq)            /* 8192 */
#define QSZ   (Bsz * Hn * Nseq * Dh)  /* 6291456 */

// ---------------- scratch (device globals; no allocations allowed) ----------
__device__ float g_z[2][Mrows * Cdim];    // proj output pre-LN

// bf16 hi/lo split tensors (16B-aligned: vector access)
__device__ __align__(16) __nv_bfloat16 g_xh[Mrows * Cdim],  g_xl[Mrows * Cdim];
__device__ __align__(16) __nv_bfloat16 g_wqh[2][3 * Cdim * Cdim], g_wql[2][3 * Cdim * Cdim];
__device__ __align__(16) __nv_bfloat16 g_wph[2][Cdim * Cdim],     g_wpl[2][Cdim * Cdim];
__device__ __align__(16) __nv_bfloat16 g_aoh[2][Mrows * Cdim],    g_aol[2][Mrows * Cdim];
__device__ __align__(16) __nv_bfloat16 g_qh[2][QSZ], g_ql[2][QSZ];
__device__ __align__(16) __nv_bfloat16 g_kh[2][QSZ], g_kl[2][QSZ];
__device__ __align__(16) __nv_bfloat16 g_vh[2][QSZ], g_vl[2][QSZ];

// ---------------- portable tensor-core helpers (compute_103-safe) -----------
__device__ __forceinline__ uint32_t smem_to_u32(const void* p) {
    uint32_t a;
    asm("{ .reg .u64 t; cvta.to.shared.u64 t, %1; cvt.u32.u64 %0, t; }"
        : "=r"(a) : "l"(p));
    return a;
}
__device__ __forceinline__ void ldsm4(uint32_t* r, uint32_t addr) {
    asm volatile("ldmatrix.sync.aligned.m8n8.x4.shared.b16 {%0,%1,%2,%3}, [%4];"
        : "=r"(r[0]), "=r"(r[1]), "=r"(r[2]), "=r"(r[3]) : "r"(addr));
}
__device__ __forceinline__ void mma16816(float* d, const uint32_t* a,
                                         uint32_t b0, uint32_t b1) {
    asm volatile("mma.sync.aligned.m16n8k16.row.col.f32.bf16.bf16.f32 "
        "{%0,%1,%2,%3}, {%4,%5,%6,%7}, {%8,%9}, {%0,%1,%2,%3};"
        : "+f"(d[0]), "+f"(d[1]), "+f"(d[2]), "+f"(d[3])
        : "r"(a[0]), "r"(a[1]), "r"(a[2]), "r"(a[3]), "r"(b0), "r"(b1));
}

union BU { __nv_bfloat16 b; unsigned short u; };
__device__ __forceinline__ void split2(float x, unsigned short& h, unsigned short& l) {
    BU hh, ll;
    hh.b = __float2bfloat16(x);
    ll.b = __float2bfloat16(x - __bfloat162float(hh.b));
    h = hh.u; l = ll.u;
}
__device__ __forceinline__ float joinf(__nv_bfloat16 h, __nv_bfloat16 l) {
    return __bfloat162float(h) + __bfloat162float(l);
}

// ---------------- fp32 -> bf16 hi/lo split -----------------------------------
__global__ void __launch_bounds__(256) cvt_kernel(
    const float4* __restrict__ s, __nv_bfloat162* __restrict__ h,
    __nv_bfloat162* __restrict__ l, int n4)
{
    int i = blockIdx.x * 256 + threadIdx.x;
    if (i >= n4) return;
    float4 v = s[i];
    __nv_bfloat16 h0 = __float2bfloat16(v.x), h1 = __float2bfloat16(v.y);
    __nv_bfloat16 h2 = __float2bfloat16(v.z), h3 = __float2bfloat16(v.w);
    h[i * 2 + 0] = __nv_bfloat162(h0, h1);
    h[i * 2 + 1] = __nv_bfloat162(h2, h3);
    l[i * 2 + 0] = __nv_bfloat162(__float2bfloat16(v.x - __bfloat162float(h0)),
                                  __float2bfloat16(v.y - __bfloat162float(h1)));
    l[i * 2 + 1] = __nv_bfloat162(__float2bfloat16(v.z - __bfloat162float(h2)),
                                  __float2bfloat16(v.w - __bfloat162float(h3)));
}

// ---------------- HMMA GEMM: C[m,n] = sum_k A[m,k]*W[n,k] --------------------
// BM=BN=128, BK=32, 8 warps (4m x 2n), m16n8k16 bf16 Karatsuba.
// MODE 0: qkv -> split-write g_{q,k,v}{h,l}.  MODE 1: proj + bias -> g_z fp32.
#define SROW 40
#define MATS (128 * SROW)

template <int MODE>
__global__ void __launch_bounds__(256) mma_gemm_kernel(
    const __nv_bfloat16* __restrict__ Ah0, const __nv_bfloat16* __restrict__ Al0,
    const float* __restrict__ bias0, const float* __restrict__ bias1)
{
    __shared__ __align__(16) __nv_bfloat16 sb[4 * MATS];   // Ah | Al | Bh | Bl

    const int z = blockIdx.z, tid = threadIdx.x;
    const int wid = tid >> 5, lane = tid & 31;
    const int bm = blockIdx.y * 128, bn = blockIdx.x * 128;
    const int wm = (wid >> 1) * 32, wn = (wid & 1) * 64;

    const __nv_bfloat16* src[4] = {
        (MODE == 0) ? Ah0 : g_aoh[z], (MODE == 0) ? Al0 : g_aol[z],
        (MODE == 0) ? g_wqh[z] : g_wph[z], (MODE == 0) ? g_wql[z] : g_wpl[z] };
    const int rb[4] = {bm, bm, bn, bn};

    const int prow = tid >> 2;
    const int pseg = (tid & 3) * 8;

    uint4 pre[4][2];
    #pragma unroll
    for (int m = 0; m < 4; m++)
        #pragma unroll
        for (int it = 0; it < 2; it++)
            pre[m][it] = *(const uint4*)(src[m] +
                (size_t)(rb[m] + prow + it * 64) * Cdim + pseg);

    float acc[2][8][4] = {};
    const uint32_t sbase = smem_to_u32(sb);

    for (int c = 0; c < 24; c++) {
        __syncthreads();
        #pragma unroll
        for (int m = 0; m < 4; m++)
            #pragma unroll
            for (int it = 0; it < 2; it++)
                *(uint4*)&sb[m * MATS + (prow + it * 64) * SROW + pseg] = pre[m][it];
        __syncthreads();
        if (c < 23) {
            const int kc = (c + 1) * 32;
            #pragma unroll
            for (int m = 0; m < 4; m++)
                #pragma unroll
                for (int it = 0; it < 2; it++)
                    pre[m][it] = *(const uint4*)(src[m] +
                        (size_t)(rb[m] + prow + it * 64) * Cdim + kc + pseg);
        }
        #pragma unroll
        for (int ks = 0; ks < 2; ks++) {
            const uint32_t koff = (uint32_t)(ks * 16 + (lane >> 4) * 8) * 2;
            uint32_t ah[2][4], al[2][4];
            #pragma unroll
            for (int mt = 0; mt < 2; mt++) {
                uint32_t ro = (uint32_t)(wm + mt * 16 + (lane & 15)) * SROW * 2 + koff;
                ldsm4(ah[mt], sbase + ro);
                ldsm4(al[mt], sbase + MATS * 2 + ro);
            }
            #pragma unroll
            for (int u = 0; u < 4; u++) {
                uint32_t ro = (uint32_t)(wn + u * 16 + (lane & 15)) * SROW * 2 + koff;
                uint32_t bh[4], bl[4];
                ldsm4(bh, sbase + 2 * MATS * 2 + ro);
                ldsm4(bl, sbase + 3 * MATS * 2 + ro);
                #pragma unroll
                for (int mt = 0; mt < 2; mt++) {
                    #pragma unroll
                    for (int hf = 0; hf < 2; hf++) {
                        float* d = acc[mt][u * 2 + hf];
                        uint32_t b0 = hf ? bh[1] : bh[0], b1 = hf ? bh[3] : bh[2];
                        uint32_t l0 = hf ? bl[1] : bl[0], l1 = hf ? bl[3] : bl[2];
                        mma16816(d, ah[mt], b0, b1);
                        mma16816(d, ah[mt], l0, l1);
                        mma16816(d, al[mt], b0, b1);
                    }
                }
            }
        }
    }

    const int g = lane >> 2, cc = (lane & 3) * 2;
    #pragma unroll
    for (int mt = 0; mt < 2; mt++) {
        #pragma unroll
        for (int nt = 0; nt < 8; nt++) {
            const int n0 = bn + wn + nt * 8 + cc;
            const int m0 = bm + wm + mt * 16 + g;
            const float* a = acc[mt][nt];
            if (MODE == 0) {
                int which = n0 / Cdim, h = (n0 % Cdim) / Dh, d0 = n0 % Dh;
                __nv_bfloat16* dh = (which == 0) ? g_qh[z] : (which == 1) ? g_kh[z] : g_vh[z];
                __nv_bfloat16* dl = (which == 0) ? g_ql[z] : (which == 1) ? g_kl[z] : g_vl[z];
                unsigned short h0, l0, h1, l1;
                int b0i = m0 >> 10, nn0 = m0 & 1023;
                size_t i0 = (((size_t)b0i * Hn + h) * Nseq + nn0) * Dh + d0;
                split2(a[0], h0, l0); split2(a[1], h1, l1);
                *(uint32_t*)&dh[i0] = (uint32_t)h0 | ((uint32_t)h1 << 16);
                *(uint32_t*)&dl[i0] = (uint32_t)l0 | ((uint32_t)l1 << 16);
                int m1 = m0 + 8, b1i = m1 >> 10, nn1 = m1 & 1023;
                size_t i1 = (((size_t)b1i * Hn + h) * Nseq + nn1) * Dh + d0;
                split2(a[2], h0, l0); split2(a[3], h1, l1);
                *(uint32_t*)&dh[i1] = (uint32_t)h0 | ((uint32_t)h1 << 16);
                *(uint32_t*)&dl[i1] = (uint32_t)l0 | ((uint32_t)l1 << 16);
            } else {
                const float* bias = z ? bias1 : bias0;
                float bx0 = bias[n0], bx1 = bias[n0 + 1];
                *(float2*)&g_z[z][(size_t)m0 * Cdim + n0] =
                    make_float2(a[0] + bx0, a[1] + bx1);
                *(float2*)&g_z[z][(size_t)(m0 + 8) * Cdim + n0] =
                    make_float2(a[2] + bx0, a[3] + bx1);
            }
        }
    }
}

// ---------------- Gram-Schmidt ortho + saliency (warp per (b,n)) ------------
__global__ void __launch_bounds__(128) ortho_kernel(
    const float* __restrict__ orth_scale_p, float* __restrict__ sal_out)
{
    int warp = (blockIdx.x * blockDim.x + threadIdx.x) >> 5;
    int lane = threadIdx.x & 31;
    if (warp >= Mrows) return;
    int b = warp >> 10, nn = warp & 1023;

    float scale = fminf(fmaxf(*orth_scale_p, 0.f), 1.f);
    float sal = 0.f;
    #pragma unroll
    for (int h = 0; h < Hn; h++) {
        size_t base = (((size_t)b * Hn + h) * Nseq + nn) * Dh;
        float qi0 = joinf(g_qh[0][base + lane],      g_ql[0][base + lane]);
        float qi1 = joinf(g_qh[0][base + 32 + lane], g_ql[0][base + 32 + lane]);
        float qc0 = joinf(g_qh[1][base + lane],      g_ql[1][base + lane]);
        float qc1 = joinf(g_qh[1][base + 32 + lane], g_ql[1][base + 32 + lane]);
        float dot = qi0 * qc0 + qi1 * qc1;
        float nsq = qc0 * qc0 + qc1 * qc1;
        #pragma unroll
        for (int o = 16; o > 0; o >>= 1) {
            dot += __shfl_xor_sync(0xffffffffu, dot, o);
            nsq += __shfl_xor_sync(0xffffffffu, nsq, o);
        }
        nsq += 1e-5f;
        float coeff = fminf(fmaxf(dot / nsq, -1.f), 1.f);
        float f = scale * coeff;
        unsigned short sh, sl;
        BU t;
        split2(qi0 - f * qc0, sh, sl);
        t.u = sh; g_qh[0][base + lane] = t.b;  t.u = sl; g_ql[0][base + lane] = t.b;
        split2(qi1 - f * qc1, sh, sl);
        t.u = sh; g_qh[0][base + 32 + lane] = t.b;  t.u = sl; g_ql[0][base + 32 + lane] = t.b;
        sal += fabsf(dot) * rsqrtf(nsq);
    }
    if (lane == 0)
        sal_out[warp] = fminf(sal * (1.f / (float)Hn), 1.f);
}

// ---------------- attention: 128q x 128kv, HMMA bf16 Karatsuba ---------------
// clip(s,-20,20) then softmax == exp(s-20)/sum(exp(s-20)) exactly (max<=20).
// smem (bf16 units): Qh 0 | Ql 9216 | Kh 18432 / Vth 18432 | Kl 27648 /
// Vtl 27136 | Ph 36864 | Pl 54272 | end 71680; denom fp32 at byte 143360.
#define AQH 0
#define AQL 9216
#define AKH 18432
#define AKL 27648
#define AVTH 18432
#define AVTL 27136
#define APH 36864
#define APL 54272
#define ATTN_SMEM_BYTES (71680 * 2 + 512)    /* 143872 */

__global__ void __launch_bounds__(256, 1) attn_kernel()
{
    extern __shared__ __align__(16) __nv_bfloat16 smb[];
    float* denom = (float*)(smb + 71680);

    const int z = blockIdx.z, bh = blockIdx.y, q0 = blockIdx.x * 128;
    const int tid = threadIdx.x, wid = tid >> 5, lane = tid & 31;
    const int wm = (wid >> 1) * 32, wn = (wid & 1) * 64, wnd = (wid & 1) * 32;
    const int g = lane >> 2, cc = (lane & 3) * 2;
    const size_t hb = (size_t)bh * Nseq * Dh;
    const __nv_bfloat16 *Qh = g_qh[z] + hb, *Ql = g_ql[z] + hb;
    const __nv_bfloat16 *Kh = g_kh[z] + hb, *Kl = g_kl[z] + hb;
    const __nv_bfloat16 *Vh = g_vh[z] + hb, *Vl = g_vl[z] + hb;
    const uint32_t sb = smem_to_u32(smb);

    // resident Q tile (h,l): rows q0..q0+127, 64 bf16 each, stride 72
    #pragma unroll
    for (int it = 0; it < 4; it++) {
        int u = tid + it * 256;
        int row = u >> 3, seg = (u & 7) * 8;
        *(uint4*)&smb[AQH + row * 72 + seg] = *(const uint4*)(Qh + (size_t)(q0 + row) * Dh + seg);
        *(uint4*)&smb[AQL + row * 72 + seg] = *(const uint4*)(Ql + (size_t)(q0 + row) * Dh + seg);
    }
    if (tid < 128) denom[tid] = 0.f;

    float oacc[2][4][4] = {};
    float rp[2][2] = {};

    for (int j0 = 0; j0 < Nseq; j0 += 128) {
        __syncthreads();   // PV reads of prior tile done; denom/Q ready first iter
        #pragma unroll
        for (int it = 0; it < 4; it++) {
            int u = tid + it * 256;
            int row = u >> 3, seg = (u & 7) * 8;
            *(uint4*)&smb[AKH + row * 72 + seg] = *(const uint4*)(Kh + (size_t)(j0 + row) * Dh + seg);
            *(uint4*)&smb[AKL + row * 72 + seg] = *(const uint4*)(Kl + (size_t)(j0 + row) * Dh + seg);
        }
        __syncthreads();

        // ---- S = Q K^T (Karatsuba) ----
        float sacc[2][8][4] = {};
        #pragma unroll
        for (int ks = 0; ks < 4; ks++) {
            const uint32_t koff = (uint32_t)(ks * 16 + (lane >> 4) * 8) * 2;
            uint32_t qhf[2][4], qlf[2][4];
            #pragma unroll
            for (int mt = 0; mt < 2; mt++) {
                uint32_t ro = (uint32_t)(wm + mt * 16 + (lane & 15)) * 144 + koff;
                ldsm4(qhf[mt], sb + AQH * 2 + ro);
                ldsm4(qlf[mt], sb + AQL * 2 + ro);
            }
            #pragma unroll
            for (int u = 0; u < 4; u++) {
                uint32_t ro = (uint32_t)(wn + u * 16 + (lane & 15)) * 144 + koff;
                uint32_t khf[4], klf[4];
                ldsm4(khf, sb + AKH * 2 + ro);
                ldsm4(klf, sb + AKL * 2 + ro);
                #pragma unroll
                for (int mt = 0; mt < 2; mt++) {
                    #pragma unroll
                    for (int hf = 0; hf < 2; hf++) {
                        float* d = sacc[mt][u * 2 + hf];
                        uint32_t b0 = hf ? khf[1] : khf[0], b1 = hf ? khf[3] : khf[2];
                        uint32_t l0 = hf ? klf[1] : klf[0], l1 = hf ? klf[3] : klf[2];
                        mma16816(d, qhf[mt], b0, b1);
                        mma16816(d, qhf[mt], l0, l1);
                        mma16816(d, qlf[mt], b0, b1);
                    }
                }
            }
        }

        // ---- softmax numerator: p = exp(clip(s/8)-20); P -> smem (h,l) ----
        #pragma unroll
        for (int mt = 0; mt < 2; mt++) {
            int r0 = wm + mt * 16 + g;
            #pragma unroll
            for (int nt = 0; nt < 8; nt++) {
                const float* s = sacc[mt][nt];
                float p0 = __expf(fminf(fmaxf(s[0] * 0.125f, -20.f), 20.f) - 20.f);
                float p1 = __expf(fminf(fmaxf(s[1] * 0.125f, -20.f), 20.f) - 20.f);
                float p2 = __expf(fminf(fmaxf(s[2] * 0.125f, -20.f), 20.f) - 20.f);
                float p3 = __expf(fminf(fmaxf(s[3] * 0.125f, -20.f), 20.f) - 20.f);
                rp[mt][0] += p0 + p1;
                rp[mt][1] += p2 + p3;
                int col = wn + nt * 8 + cc;
                unsigned short h0, l0, h1, l1;
                split2(p0, h0, l0); split2(p1, h1, l1);
                *(uint32_t*)&smb[APH + r0 * 136 + col] = (uint32_t)h0 | ((uint32_t)h1 << 16);
                *(uint32_t*)&smb[APL + r0 * 136 + col] = (uint32_t)l0 | ((uint32_t)l1 << 16);
                split2(p2, h0, l0); split2(p3, h1, l1);
                *(uint32_t*)&smb[APH + (r0 + 8) * 136 + col] = (uint32_t)h0 | ((uint32_t)h1 << 16);
                *(uint32_t*)&smb[APL + (r0 + 8) * 136 + col] = (uint32_t)l0 | ((uint32_t)l1 << 16);
            }
        }
        __syncthreads();   // P complete; K reads done -> reuse KV buffer for V^T

        // ---- V^T into KV buffer: Vt[d][j], stride 136 ----
        #pragma unroll
        for (int it = 0; it < 2; it++) {
            int u = tid + it * 256;
            int r = u & 63, seg = u >> 6;        // seg 0..7
            int d0 = seg * 8;
            uint4 a0 = *(const uint4*)(Vh + (size_t)(j0 + 2 * r) * Dh + d0);
            uint4 a1 = *(const uint4*)(Vh + (size_t)(j0 + 2 * r + 1) * Dh + d0);
            const unsigned short* as = (const unsigned short*)&a0;
            const unsigned short* bs = (const unsigned short*)&a1;
            #pragma unroll
            for (int i = 0; i < 8; i++)
                *(uint32_t*)&smb[AVTH + (d0 + i) * 136 + 2 * r] =
                    (uint32_t)as[i] | ((uint32_t)bs[i] << 16);
            uint4 c0 = *(const uint4*)(Vl + (size_t)(j0 + 2 * r) * Dh + d0);
            uint4 c1 = *(const uint4*)(Vl + (size_t)(j0 + 2 * r + 1) * Dh + d0);
            const unsigned short* cs = (const unsigned short*)&c0;
            const unsigned short* ds = (const unsigned short*)&c1;
            #pragma unroll
            for (int i = 0; i < 8; i++)
                *(uint32_t*)&smb[AVTL + (d0 + i) * 136 + 2 * r] =
                    (uint32_t)cs[i] | ((uint32_t)ds[i] << 16);
        }
        __syncthreads();

        // ---- O += P V (Karatsuba) ----
        #pragma unroll
        for (int ks = 0; ks < 8; ks++) {
            const uint32_t koff = (uint32_t)(ks * 16 + (lane >> 4) * 8) * 2;
            uint32_t phf[2][4], plf[2][4];
            #pragma unroll
            for (int mt = 0; mt < 2; mt++) {
                uint32_t ro = (uint32_t)(wm + mt * 16 + (lane & 15)) * 272 + koff;
                ldsm4(phf[mt], sb + APH * 2 + ro);
                ldsm4(plf[mt], sb + APL * 2 + ro);
            }
            #pragma unroll
            for (int u = 0; u < 2; u++) {
                uint32_t ro = (uint32_t)(wnd + u * 16 + (lane & 15)) * 272 + koff;
                uint32_t vhf[4], vlf[4];
                ldsm4(vhf, sb + AVTH * 2 + ro);
                ldsm4(vlf, sb + AVTL * 2 + ro);
                #pragma unroll
                for (int mt = 0; mt < 2; mt++) {
                    #pragma unroll
                    for (int hf = 0; hf < 2; hf++) {
                        float* d = oacc[mt][u * 2 + hf];
                        uint32_t b0 = hf ? vhf[1] : vhf[0], b1 = hf ? vhf[3] : vhf[2];
                        uint32_t l0 = hf ? vlf[1] : vlf[0], l1 = hf ? vlf[3] : vlf[2];
                        mma16816(d, phf[mt], b0, b1);
                        mma16816(d, phf[mt], l0, l1);
                        mma16816(d, plf[mt], b0, b1);
                    }
                }
            }
        }
    }

    // ---- denominators ----
    #pragma unroll
    for (int mt = 0; mt < 2; mt++)
        #pragma unroll
        for (int hfi = 0; hfi < 2; hfi++) {
            float v = rp[mt][hfi];
            v += __shfl_xor_sync(0xffffffffu, v, 1);
            v += __shfl_xor_sync(0xffffffffu, v, 2);
            if ((lane & 3) == 0)
                atomicAdd(&denom[wm + mt * 16 + hfi * 8 + g], v);
        }
    __syncthreads();

    // ---- epilogue: ao = O / denom, split-written to aoh/aol ----
    const int b = bh / Hn, h = bh % Hn;
    __nv_bfloat16* aoh = g_aoh[z];
    __nv_bfloat16* aol = g_aol[z];
    #pragma unroll
    for (int mt = 0; mt < 2; mt++) {
        int r0 = wm + mt * 16 + g;
        float inv0 = 1.f / denom[r0], inv1 = 1.f / denom[r0 + 8];
        #pragma unroll
        for (int nt = 0; nt < 4; nt++) {
            const float* a = oacc[mt][nt];
            int col = h * Dh + wnd + nt * 8 + cc;
            unsigned short h0, l0, h1, l1;
            size_t i0 = ((size_t)(b * Nseq + q0 + r0)) * Cdim + col;
            split2(a[0] * inv0, h0, l0); split2(a[1] * inv0, h1, l1);
            *(uint32_t*)&aoh[i0] = (uint32_t)h0 | ((uint32_t)h1 << 16);
            *(uint32_t*)&aol[i0] = (uint32_t)l0 | ((uint32_t)l1 << 16);
            size_t i1 = ((size_t)(b * Nseq + q0 + r0 + 8)) * Cdim + col;
            split2(a[2] * inv1, h0, l0); split2(a[3] * inv1, h1, l1);
            *(uint32_t*)&aoh[i1] = (uint32_t)h0 | ((uint32_t)h1 << 16);
            *(uint32_t*)&aol[i1] = (uint32_t)l0 | ((uint32_t)l1 << 16);
        }
    }
}

// ---------------- LayerNorm (row per block) ---------------------------------
__global__ void __launch_bounds__(256) ln_kernel(
    const float* __restrict__ w0, const float* __restrict__ b0,
    const float* __restrict__ w1, const float* __restrict__ b1,
    float* __restrict__ out)
{
    const int z = blockIdx.y, m = blockIdx.x, tid = threadIdx.x;
    const float* row = g_z[z] + (size_t)m * Cdim;
    float v0 = row[tid], v1 = row[tid + 256], v2 = row[tid + 512];
    float s  = v0 + v1 + v2;
    float sq = v0 * v0 + v1 * v1 + v2 * v2;
    #pragma unroll
    for (int o = 16; o > 0; o >>= 1) {
        s  += __shfl_xor_sync(0xffffffffu, s,  o);
        sq += __shfl_xor_sync(0xffffffffu, sq, o);
    }
    __shared__ float ss[8], sqs[8];
    int wid = tid >> 5, lane = tid & 31;
    if (lane == 0) { ss[wid] = s; sqs[wid] = sq; }
    __syncthreads();
    if (tid == 0) {
        float S = 0.f, Qq = 0.f;
        #pragma unroll
        for (int i = 0; i < 8; i++) { S += ss[i]; Qq += sqs[i]; }
        float mean = S * (1.f / (float)Cdim);
        float var  = Qq * (1.f / (float)Cdim) - mean * mean;
        ss[0] = mean; sqs[0] = rsqrtf(var + 1e-5f);
    }
    __syncthreads();
    float mean = ss[0], rstd = sqs[0];
    const float* w = z ? w1 : w0;
    const float* bb = z ? b1 : b0;
    float* o = out + (size_t)z * Mrows * Cdim + (size_t)m * Cdim;
    o[tid]       = (v0 - mean) * rstd * w[tid]       + bb[tid];
    o[tid + 256] = (v1 - mean) * rstd * w[tid + 256] + bb[tid + 256];
    o[tid + 512] = (v2 - mean) * rstd * w[tid + 512] + bb[tid + 512];
}

// ---------------- launch -----------------------------------------------------
static void cvt(const float* src, __nv_bfloat16* hi, __nv_bfloat16* lo, int n) {
    int n4 = n / 4;
    cvt_kernel<<<(n4 + 255) / 256, 256>>>(
        (const float4*)src, (__nv_bfloat162*)hi, (__nv_bfloat162*)lo, n4);
}

extern "C" void kernel_launch(void* const* d_in, const int* in_sizes, int n_in,
                              void* d_out, int out_size)
{
    const float* x        = (const float*)d_in[0];
    const float* wqkv_id  = (const float*)d_in[1];
    const float* wqkv_cl  = (const float*)d_in[2];
    const float* wp_id    = (const float*)d_in[3];
    const float* bp_id    = (const float*)d_in[4];
    const float* wp_cl    = (const float*)d_in[5];
    const float* bp_cl    = (const float*)d_in[6];
    const float* lnw_id   = (const float*)d_in[7];
    const float* lnb_id   = (const float*)d_in[8];
    const float* lnw_cl   = (const float*)d_in[9];
    const float* lnb_cl   = (const float*)d_in[10];
    const float* orth     = (const float*)d_in[11];
    float* out = (float*)d_out;

    cudaFuncSetAttribute(attn_kernel,
                         cudaFuncAttributeMaxDynamicSharedMemorySize, ATTN_SMEM_BYTES);

    __nv_bfloat16 *xh, *xl, *wqh, *wql, *wph, *wpl;
    cudaGetSymbolAddress((void**)&xh,  g_xh);
    cudaGetSymbolAddress((void**)&xl,  g_xl);
    cudaGetSymbolAddress((void**)&wqh, g_wqh);
    cudaGetSymbolAddress((void**)&wql, g_wql);
    cudaGetSymbolAddress((void**)&wph, g_wph);
    cudaGetSymbolAddress((void**)&wpl, g_wpl);

    // 0. fp32 -> bf16 hi/lo splits (inputs + weights only)
    cvt(x,        xh,                       xl,                       Mrows * Cdim);
    cvt(wqkv_id,  wqh,                      wql,                      3 * Cdim * Cdim);
    cvt(wqkv_cl,  wqh + 3 * Cdim * Cdim,    wql + 3 * Cdim * Cdim,    3 * Cdim * Cdim);
    cvt(wp_id,    wph,                      wpl,                      Cdim * Cdim);
    cvt(wp_cl,    wph + Cdim * Cdim,        wpl + Cdim * Cdim,        Cdim * Cdim);

    // 1. QKV GEMMs (HMMA, split-write q/k/v)
    dim3 g1(3 * Cdim / 128, Mrows / 128, 2);      // (18, 64, 2)
    mma_gemm_kernel<0><<<g1, 256>>>(xh, xl, nullptr, nullptr);

    // 2. ortho projection of q_id + saliency
    ortho_kernel<<<Mrows / 4, 128>>>(orth, out + 2 * (size_t)Mrows * Cdim);

    // 3. attention (HMMA, writes aoh/aol directly)
    attn_kernel<<<dim3(Nseq / 128, Bsz * Hn, 2), 256, ATTN_SMEM_BYTES>>>();

    // 4. proj + bias (HMMA) -> g_z
    dim3 g2(Cdim / 128, Mrows / 128, 2);          // (6, 64, 2)
    mma_gemm_kernel<1><<<g2, 256>>>(nullptr, nullptr, bp_id, bp_cl);

    // 5. layernorm -> d_out
    ln_kernel<<<dim3(Mrows, 2), 256>>>(lnw_id, lnb_id, lnw_cl, lnb_cl, out);
}